// round 12
// baseline (speedup 1.0000x reference)
#include <cuda_runtime.h>

// DynamicLIF persistent kernel for GB300 (sm_103a), round 12.
// Base = R10 (65.0us). KEY CHANGE: software-pipelined x loads across the
// tau barrier. mem state moves to SHARED (32KB/block, frees 32 regs); the
// next step's x tile is loaded into 32 REGISTERS (plain LDG.128, 1.82cyc
// issue -- NOT cp.async (8cyc issue, R2 disaster) and NOT prefetch.L2
// (L1tex pollution, R3/R8)) during the current step's fused pass. After the
// poll, the pass starts HOT: zero cold DRAM latency on the critical path.
// Fused single pass per slice: LDS mem -> FMA(tau, xv) -> partial+shfl ->
// spike STG -> reset STS -> refill xv with x[t+1] LDG.
// Publish now follows a ~1us compute pass (was gated by a 2.8us cold load
// phase) -> coordinator MLP starts earlier; loads complete during the
// store-drain + MLP + poll window.
// All tau-feeding values/order byte-identical to R10 (rel_err 0.0).

#define NB 32          // batch
#define NT 8           // time steps
#define NC 128         // channels
#define HW_ 1024       // H*W
#define CR 32          // C / red
#define THREADS 256
#define RPB 8          // channel rows per block
#define BPB 16         // streaming blocks per batch
#define NSTREAM (NB * BPB)       // 512
#define NBLOCKS (NSTREAM + NB)   // 544 (32 coordinators)
#define PUBS (BPB * RPB)         // 128 count-releases per batch per step
#define CPAD 64        // 256B stride for g_count (unsigned)
#define SPAD 32        // 256B stride for g_sync (u64)

__device__ float              g_sums[NB * NC];
__device__ unsigned           g_count[NB * CPAD]; // zero at launch; coord resets at end
__device__ unsigned long long g_sync[NB * SPAD];  // (gen<<32)|tau_bits, monotonic gen

__device__ __forceinline__ unsigned ld_acquire_u32(const unsigned* p) {
    unsigned v;
    asm volatile("ld.acquire.gpu.global.u32 %0, [%1];" : "=r"(v) : "l"(p));
    return v;
}
__device__ __forceinline__ unsigned long long ld_acquire_u64(const unsigned long long* p) {
    unsigned long long v;
    asm volatile("ld.acquire.gpu.global.u64 %0, [%1];" : "=l"(v) : "l"(p));
    return v;
}
__device__ __forceinline__ void st_release_u64(unsigned long long* p, unsigned long long v) {
    asm volatile("st.release.gpu.global.u64 [%0], %1;" :: "l"(p), "l"(v));
}
__device__ __forceinline__ void red_release_add(unsigned* p, unsigned v) {
    asm volatile("red.release.gpu.global.add.u32 [%0], %1;" :: "l"(p), "r"(v));
}

__global__ void __launch_bounds__(THREADS, 4)
lif_kernel(const float* __restrict__ x,
           const float* __restrict__ w1,
           const float* __restrict__ b1,
           const float* __restrict__ w2,
           const float* __restrict__ b2,
           float* __restrict__ out)
{
    // Shared union: streaming blocks use 32KB mem buffer (+warp partials);
    // coordinators use 16KB transposed w1 (+mean). Max footprint ~33KB.
    __shared__ __align__(16) char s_raw[32768 + 256 + 16];

    const int tid = threadIdx.x;
    const int blk = blockIdx.x;
    const int lane = tid & 31;
    const int warp = tid >> 5;

    // ---------------- coordinator blocks (one per batch) ----------------
    if (blk >= NSTREAM) {
        float* s_w1t  = (float*)s_raw;              // [NC*CR] transposed
        float* s_mean = (float*)(s_raw + 16384);    // [NC]

        const int bb = blk - NSTREAM;
        unsigned*           cnt = &g_count[bb * CPAD];
        unsigned long long* syn = &g_sync[bb * SPAD];

        #pragma unroll
        for (int i = 0; i < (CR * NC) / THREADS; i++) {
            int idx = i * THREADS + tid;
            s_w1t[(idx & 127) * CR + (idx >> 7)] = w1[idx];
        }

        unsigned base_gen = 0;
        if (tid == 0) base_gen = (unsigned)(*(volatile unsigned long long*)syn >> 32);
        __syncthreads();

        #pragma unroll 1
        for (int t = 0; t < NT - 1; t++) {
            if (tid == 0) {
                unsigned tgt = (unsigned)PUBS * (unsigned)(t + 1);
                while (ld_acquire_u32(cnt) < tgt) { }
            }
            __syncthreads();   // acquire by t0 + barrier -> sums visible

            // MLP: values + order byte-identical to R10.
            if (tid < NC)
                s_mean[tid] = __ldcg(&g_sums[bb * NC + tid]) * (1.0f / 1024.0f);
            __syncthreads();
            if (tid < CR) {
                float acc = b1[tid];
                #pragma unroll
                for (int c = 0; c < NC; c++)
                    acc = fmaf(s_w1t[c * CR + tid], s_mean[c], acc);
                float e = fmaxf(acc, 0.0f);        // relu
                float p = e * w2[tid];
                p += __shfl_xor_sync(0xffffffffu, p, 16);
                p += __shfl_xor_sync(0xffffffffu, p, 8);
                p += __shfl_xor_sync(0xffffffffu, p, 4);
                p += __shfl_xor_sync(0xffffffffu, p, 2);
                p += __shfl_xor_sync(0xffffffffu, p, 1);
                if (tid == 0) {
                    float z = p + b2[0];
                    float tn = 1.0f / (1.0f + expf(-z));   // sigmoid
                    unsigned long long v =
                        ((unsigned long long)(base_gen + (unsigned)(t + 1)) << 32)
                        | (unsigned long long)__float_as_uint(tn);
                    st_release_u64(syn, v);   // gen + tau in one word
                }
            }
            __syncthreads();
        }
        if (tid == 0) *(volatile unsigned*)cnt = 0;   // replay-safe reset
        return;
    }

    // ---------------- streaming blocks ----------------
    float4* s_mem = (float4*)s_raw;                         // [RPB*THREADS]
    float (*s_warp)[RPB] = (float(*)[RPB])(s_raw + 32768);  // [8][RPB]
    float* s_tau = (float*)(s_raw + 32768 + 256);

    const int b   = blk >> 4;          // batch
    const int sub = blk & 15;          // sub-block within batch
    unsigned*           const cnt = &g_count[b * CPAD];
    unsigned long long* const syn = &g_sync[b * SPAD];

    // base_gen read precedes this block's first publish -> race-free.
    unsigned base_gen = 0;
    if (tid == 0) base_gen = (unsigned)(*(volatile unsigned long long*)syn >> 32);

    // Zero mem state in shared (thread-private slots).
    #pragma unroll
    for (int i = 0; i < RPB; i++)
        s_mem[i * THREADS + tid] = make_float4(0.f, 0.f, 0.f, 0.f);

    const size_t row_base = ((size_t)b * NT * NC + (size_t)sub * RPB) * HW_;

    // Prologue: load x[0] into registers.
    float4 xv[RPB];
    {
        const float4* xp0 = (const float4*)(x + row_base);
        #pragma unroll
        for (int i = 0; i < RPB; i++)
            xv[i] = __ldcs(xp0 + i * THREADS + tid);
    }

    float tau = 0.5f;                  // TAU0

    for (int t = 0; t < NT; t++) {
        float4* op = (float4*)(out + row_base + (size_t)t * NC * HW_);
        const float4* xpn = (const float4*)(x + row_base + (size_t)(t + 1) * NC * HW_);
        const bool need_tau  = (t < NT - 1);
        const bool need_next = (t + 1 < NT);

        // ---- fused pass: LDS mem -> FMA -> partial+shfl -> spike STG ->
        //      reset STS -> refill xv with x[t+1] (plain LDG, overlaps
        //      everything up to next consumption) ----
        #pragma unroll
        for (int i = 0; i < RPB; i++) {
            float4 m = s_mem[i * THREADS + tid];
            m.x = __fadd_rn(__fmul_rn(m.x, tau), xv[i].x);
            m.y = __fadd_rn(__fmul_rn(m.y, tau), xv[i].y);
            m.z = __fadd_rn(__fmul_rn(m.z, tau), xv[i].z);
            m.w = __fadd_rn(__fmul_rn(m.w, tau), xv[i].w);
            if (need_next)
                xv[i] = __ldcs(xpn + i * THREADS + tid);   // refill, no wait
            if (need_tau) {
                float v = (m.x + m.y) + (m.z + m.w);        // same order as R10
                v += __shfl_xor_sync(0xffffffffu, v, 16);
                v += __shfl_xor_sync(0xffffffffu, v, 8);
                v += __shfl_xor_sync(0xffffffffu, v, 4);
                v += __shfl_xor_sync(0xffffffffu, v, 2);
                v += __shfl_xor_sync(0xffffffffu, v, 1);
                if (lane == 0) s_warp[warp][i] = v;
            }
            float4 sp;
            sp.x = (m.x > 1.0f) ? 1.0f : 0.0f;
            sp.y = (m.y > 1.0f) ? 1.0f : 0.0f;
            sp.z = (m.z > 1.0f) ? 1.0f : 0.0f;
            sp.w = (m.w > 1.0f) ? 1.0f : 0.0f;
            __stcs(op + i * THREADS + tid, sp);             // issue-only cost
            m.x = (m.x > 1.0f) ? 0.0f : m.x;
            m.y = (m.y > 1.0f) ? 0.0f : m.y;
            m.z = (m.z > 1.0f) ? 0.0f : m.z;
            m.w = (m.w > 1.0f) ? 0.0f : m.w;
            s_mem[i * THREADS + tid] = m;
        }

        if (!need_tau) break;

        __syncthreads();   // s_warp complete across all 8 warps

        // ---- publish this block's 8 channel sums (identical to R10) ----
        if (tid < RPB) {
            float s = 0.f;
            #pragma unroll
            for (int w = 0; w < 8; w++) s += s_warp[w][tid];
            __stcg(&g_sums[b * NC + sub * RPB + tid], s);
            red_release_add(cnt, 1u);
        }

        // ---- single poll: generation + tau arrive together.
        //      x[t+1] loads (issued above) complete during this window. ----
        if (tid == 0) {
            unsigned tgt = base_gen + (unsigned)(t + 1);
            unsigned long long v;
            do {
                v = ld_acquire_u64(syn);
            } while ((int)((unsigned)(v >> 32) - tgt) < 0);
            *s_tau = __uint_as_float((unsigned)v);
        }
        __syncthreads();
        tau = *s_tau;
    }
}

extern "C" void kernel_launch(void* const* d_in, const int* in_sizes, int n_in,
                              void* d_out, int out_size)
{
    const float* x  = (const float*)d_in[0];
    const float* w1 = (const float*)d_in[1];
    const float* b1 = (const float*)d_in[2];
    const float* w2 = (const float*)d_in[3];
    const float* b2 = (const float*)d_in[4];
    float* out = (float*)d_out;

    lif_kernel<<<NBLOCKS, THREADS>>>(x, w1, b1, w2, b2, out);
}